// round 9
// baseline (speedup 1.0000x reference)
#include <cuda_runtime.h>
#include <cstddef>

#define HH 16
#define DD 1024
#define KD 64
#define NN 4096
#define MM 4096

// Scratch (__device__ globals: the allowed no-malloc workaround)
static __device__ float g_Q[(size_t)HH * NN * KD];   // [h][n][64]
static __device__ float g_K[(size_t)HH * MM * KD];   // [h][m][64]
static __device__ float g_V[(size_t)HH * MM * KD];   // [h][m][64]
static __device__ float g_O[(size_t)NN * (HH * KD)]; // [n][h*64+v]
static __device__ unsigned g_mbits[(size_t)NN * (MM / 32)]; // bit-packed mask (2MB)

typedef unsigned long long u64;

// ---- packed fp32x2 helpers (FFMA2 path: only reachable via PTX) ----------
__device__ __forceinline__ u64 dup2(float x) {
    u64 r; unsigned xi = __float_as_uint(x);
    asm("mov.b64 %0, {%1, %1};" : "=l"(r) : "r"(xi));
    return r;
}
__device__ __forceinline__ void ffma2(u64& d, u64 a, u64 b) {
    asm("fma.rn.f32x2 %0, %1, %2, %0;" : "+l"(d) : "l"(a), "l"(b));
}
__device__ __forceinline__ void fmul2(u64& d, u64 b) {
    asm("mul.rn.f32x2 %0, %0, %1;" : "+l"(d) : "l"(b));
}
__device__ __forceinline__ float f2lo(u64 v) { return __uint_as_float((unsigned)v); }
__device__ __forceinline__ float f2hi(u64 v) { return __uint_as_float((unsigned)(v >> 32)); }

// ---------------------------------------------------------------------------
// Bit-pack mask: one u32 word = 32 mask ints along m.
// ---------------------------------------------------------------------------
__global__ __launch_bounds__(256) void pack_mask(const int* __restrict__ mask,
                                                 unsigned* __restrict__ bits)
{
    int idx = blockIdx.x * 256 + threadIdx.x;        // 0 .. N*128-1
    const int* p = mask + (size_t)idx * 32;
    unsigned b = 0;
#pragma unroll
    for (int u = 0; u < 8; u++) {
        int4 m = ((const int4*)p)[u];
        b |= (unsigned)(m.x != 0) << (u * 4 + 0);
        b |= (unsigned)(m.y != 0) << (u * 4 + 1);
        b |= (unsigned)(m.z != 0) << (u * 4 + 2);
        b |= (unsigned)(m.w != 0) << (u * 4 + 3);
    }
    bits[idx] = b;
}

// ---------------------------------------------------------------------------
// Fused fp32 GEMM: C[128 x 128] = A[128 x K] * [W1 | W2] (two 64-wide panels).
// (unchanged from R6 — FMA-bound per wavefront analysis)
// ---------------------------------------------------------------------------
__global__ __launch_bounds__(256) void gemm2(
    const float* __restrict__ A, int lda,
    const float* __restrict__ W1b, const float* __restrict__ W2b, long wStride, int ldw,
    float* __restrict__ C1b, float* __restrict__ C2b, long cStride, int ldc, int K)
{
    __shared__ float At[32 * 132];   // [kk][rotated row]
    __shared__ float Ws[32 * 136];   // [kk][128 cols: W1 | W2]

    const int tid = threadIdx.x;
    const int tx  = tid & 15;
    const int ty  = tid >> 4;
    const int c0  = tx * 8;
    const int r0  = ty * 8;
    const int row0 = blockIdx.x * 128;
    const float* W1 = W1b + (long)blockIdx.y * wStride;
    const float* W2 = W2b + (long)blockIdx.y * wStride;

    u64 acc[4][8];
#pragma unroll
    for (int i = 0; i < 4; i++)
#pragma unroll
        for (int j = 0; j < 8; j++) acc[i][j] = 0ull;

    for (int kt = 0; kt < K; kt += 32) {
#pragma unroll
        for (int u = 0; u < 4; u++) {
            int idx = tid + u * 256;
            int r   = idx >> 3;
            int kv  = idx & 7;
            float4 v = *(const float4*)(A + (size_t)(row0 + r) * lda + kt + kv * 4);
            int rr = (r + kv * 4) & 127;
            At[(kv * 4 + 0) * 132 + rr] = v.x;
            At[(kv * 4 + 1) * 132 + rr] = v.y;
            At[(kv * 4 + 2) * 132 + rr] = v.z;
            At[(kv * 4 + 3) * 132 + rr] = v.w;
        }
#pragma unroll
        for (int u = 0; u < 4; u++) {
            int idx  = tid + u * 256;
            int half = idx >> 9;
            int kk   = (idx >> 4) & 31;
            int cv   = idx & 15;
            const float* src = (half ? W2 : W1) + (size_t)(kt + kk) * ldw + cv * 4;
            *(float4*)(Ws + kk * 136 + half * 64 + cv * 4) = *(const float4*)src;
        }
        __syncthreads();

#pragma unroll 2
        for (int kk4 = 0; kk4 < 8; kk4++) {
            int ra = (r0 + kk4 * 4) & 127;
            int rb = (r0 + 4 + kk4 * 4) & 127;
#pragma unroll
            for (int s = 0; s < 4; s++) {
                int kk = kk4 * 4 + s;
                ulonglong2 qa = *(const ulonglong2*)(At + kk * 132 + ra);
                ulonglong2 qb = *(const ulonglong2*)(At + kk * 132 + rb);
                float4 w0 = *(const float4*)(Ws + kk * 136 + c0);
                float4 w1 = *(const float4*)(Ws + kk * 136 + c0 + 4);
                u64 d0 = dup2(w0.x), d1 = dup2(w0.y), d2 = dup2(w0.z), d3 = dup2(w0.w);
                u64 d4 = dup2(w1.x), d5 = dup2(w1.y), d6 = dup2(w1.z), d7 = dup2(w1.w);
                ffma2(acc[0][0], qa.x, d0); ffma2(acc[0][1], qa.x, d1);
                ffma2(acc[0][2], qa.x, d2); ffma2(acc[0][3], qa.x, d3);
                ffma2(acc[0][4], qa.x, d4); ffma2(acc[0][5], qa.x, d5);
                ffma2(acc[0][6], qa.x, d6); ffma2(acc[0][7], qa.x, d7);
                ffma2(acc[1][0], qa.y, d0); ffma2(acc[1][1], qa.y, d1);
                ffma2(acc[1][2], qa.y, d2); ffma2(acc[1][3], qa.y, d3);
                ffma2(acc[1][4], qa.y, d4); ffma2(acc[1][5], qa.y, d5);
                ffma2(acc[1][6], qa.y, d6); ffma2(acc[1][7], qa.y, d7);
                ffma2(acc[2][0], qb.x, d0); ffma2(acc[2][1], qb.x, d1);
                ffma2(acc[2][2], qb.x, d2); ffma2(acc[2][3], qb.x, d3);
                ffma2(acc[2][4], qb.x, d4); ffma2(acc[2][5], qb.x, d5);
                ffma2(acc[2][6], qb.x, d6); ffma2(acc[2][7], qb.x, d7);
                ffma2(acc[3][0], qb.y, d0); ffma2(acc[3][1], qb.y, d1);
                ffma2(acc[3][2], qb.y, d2); ffma2(acc[3][3], qb.y, d3);
                ffma2(acc[3][4], qb.y, d4); ffma2(acc[3][5], qb.y, d5);
                ffma2(acc[3][6], qb.y, d6); ffma2(acc[3][7], qb.y, d7);
            }
        }
        __syncthreads();
    }

    float* Cp = (tx < 8)
        ? (C1b + (long)blockIdx.y * cStride + c0)
        : (C2b + (long)blockIdx.y * cStride + (c0 - 64));
#pragma unroll
    for (int i2 = 0; i2 < 4; i2++) {
        float* rlo = Cp + (size_t)(row0 + r0 + 2 * i2) * ldc;
        float* rhi = Cp + (size_t)(row0 + r0 + 2 * i2 + 1) * ldc;
        *(float4*)(rlo)     = make_float4(f2lo(acc[i2][0]), f2lo(acc[i2][1]), f2lo(acc[i2][2]), f2lo(acc[i2][3]));
        *(float4*)(rlo + 4) = make_float4(f2lo(acc[i2][4]), f2lo(acc[i2][5]), f2lo(acc[i2][6]), f2lo(acc[i2][7]));
        *(float4*)(rhi)     = make_float4(f2hi(acc[i2][0]), f2hi(acc[i2][1]), f2hi(acc[i2][2]), f2hi(acc[i2][3]));
        *(float4*)(rhi + 4) = make_float4(f2hi(acc[i2][4]), f2hi(acc[i2][5]), f2hi(acc[i2][6]), f2hi(acc[i2][7]));
    }
}

// ---------------------------------------------------------------------------
// Flash attention fp32, BM=64 x BN=64, 256 threads, 3 CTAs/SM.
// Warp tile 32 rows x 16 cols (lane = 8 lr x 4 lc) -> minimal smem bytes/FMA.
// Row softmax spans 4 warps: warps exchange slice maxima through smem each
// tile (consistent-max protocol), so every Pt entry shares one scaling and PV
// may sum all jm; the row denominators l are merged once at the end.
// P stored transposed (Pt[jm][row]) -> conflict-free LDS.128 in PV.
// ---------------------------------------------------------------------------
__global__ __launch_bounds__(256, 3) void attn_kernel(void)
{
    extern __shared__ float sm[];
    float* Qt  = sm;                  // [64 kd][68 rows]
    float* Kt  = Qt + 64 * 68;        // [64 kd][68 rotated cols]
    float* Vs  = Kt + 64 * 68;        // [64 jm][68 v-cols]
    float* Pt  = Vs + 64 * 68;        // [64 jm][68 rows]  (transposed P)
    float* Msl = Pt + 64 * 68;        // [64 rows][4 slices]: tile max / final l

    const int tid  = threadIdx.x;
    const int lane = tid & 31;
    const int wrp  = tid >> 5;
    const int lr   = lane >> 2;
    const int lc   = lane & 3;
    const int wr   = wrp & 1;         // 2 row-groups of warps
    const int wc   = wrp >> 1;        // 4 col-slices of warps
    const int r0   = wr * 32 + lr * 4;
    const int c0   = wc * 16 + lc * 4;
    const int shift = c0 & 31;
    const int h  = blockIdx.x;        // heads fastest -> K/V + mask L2 reuse
    const int n0 = blockIdx.y * 64;

    const float* Qh = g_Q + (size_t)h * NN * KD;
    const float* Kh = g_K + (size_t)h * MM * KD;
    const float* Vh = g_V + (size_t)h * MM * KD;

    // Load Q tile 64x64, kd-major (one-time; unrotated), tid-mapped
#pragma unroll
    for (int u = 0; u < 4; u++) {
        int idx = tid + u * 256;
        int r   = idx >> 4;           // 0..63
        int kv  = idx & 15;
        float4 v = *(const float4*)(Qh + (size_t)(n0 + r) * KD + kv * 4);
        Qt[(kv * 4 + 0) * 68 + r] = v.x;
        Qt[(kv * 4 + 1) * 68 + r] = v.y;
        Qt[(kv * 4 + 2) * 68 + r] = v.z;
        Qt[(kv * 4 + 3) * 68 + r] = v.w;
    }

    float mrow[4], lrow[4];
    u64 o2[4][2];                     // [row][v-col pair]
#pragma unroll
    for (int i = 0; i < 4; i++) {
        mrow[i] = -1e30f; lrow[i] = 0.0f;
        o2[i][0] = 0ull; o2[i][1] = 0ull;
    }

    for (int mt = 0; mt < MM; mt += 64) {
        __syncthreads();              // prior PV readers of Vs/Pt, QK readers of Kt done

        // Load K (kd-major, rotated) + V (row-major) 64x64 tiles, tid-mapped
#pragma unroll
        for (int u = 0; u < 4; u++) {
            int idx = tid + u * 256;
            int j   = idx >> 4;       // 0..63
            int kv  = idx & 15;
            float4 kf = *(const float4*)(Kh + (size_t)(mt + j) * KD + kv * 4);
            int jr = (j + kv * 4) & 63;
            Kt[(kv * 4 + 0) * 68 + jr] = kf.x;
            Kt[(kv * 4 + 1) * 68 + jr] = kf.y;
            Kt[(kv * 4 + 2) * 68 + jr] = kf.z;
            Kt[(kv * 4 + 3) * 68 + jr] = kf.w;
            *(float4*)(Vs + j * 68 + kv * 4) =
                *(const float4*)(Vh + (size_t)(mt + j) * KD + kv * 4);
        }

        // Prefetch mask bits (consumed after QK -> LDG latency hidden)
        unsigned mw[4];
        {
            int widx = (mt + c0) >> 5;
#pragma unroll
            for (int i = 0; i < 4; i++)
                mw[i] = g_mbits[(size_t)(n0 + r0 + i) * (MM / 32) + widx];
        }
        __syncthreads();

        // ---- S = Q K^T (row-pair packed) ----
        u64 s2[2][4];
#pragma unroll
        for (int i = 0; i < 2; i++)
#pragma unroll
            for (int j = 0; j < 4; j++) s2[i][j] = 0ull;

#pragma unroll 4
        for (int kd4 = 0; kd4 < 16; kd4++) {
            int cc = (c0 + kd4 * 4) & 63;   // rotated col start
#pragma unroll
            for (int s = 0; s < 4; s++) {
                int kd = kd4 * 4 + s;
                ulonglong2 qa = *(const ulonglong2*)(Qt + kd * 68 + r0);
                float4 kf = *(const float4*)(Kt + kd * 68 + cc);
                u64 k0 = dup2(kf.x), k1 = dup2(kf.y), k2 = dup2(kf.z), k3 = dup2(kf.w);
                ffma2(s2[0][0], qa.x, k0); ffma2(s2[0][1], qa.x, k1);
                ffma2(s2[0][2], qa.x, k2); ffma2(s2[0][3], qa.x, k3);
                ffma2(s2[1][0], qa.y, k0); ffma2(s2[1][1], qa.y, k1);
                ffma2(s2[1][2], qa.y, k2); ffma2(s2[1][3], qa.y, k3);
            }
        }

        // ---- phase 1: mask + per-slice max -> smem ----
        float pv[4][4];
#pragma unroll
        for (int i = 0; i < 4; i++) {
            const int p = i >> 1, sub = i & 1;
            float v0 = sub ? f2hi(s2[p][0]) : f2lo(s2[p][0]);
            float v1 = sub ? f2hi(s2[p][1]) : f2lo(s2[p][1]);
            float v2 = sub ? f2hi(s2[p][2]) : f2lo(s2[p][2]);
            float v3 = sub ? f2hi(s2[p][3]) : f2lo(s2[p][3]);
            unsigned bits = (mw[i] >> shift) & 0xFu;
            if (!(bits & 1u)) v0 = -1e30f;
            if (!(bits & 2u)) v1 = -1e30f;
            if (!(bits & 4u)) v2 = -1e30f;
            if (!(bits & 8u)) v3 = -1e30f;
            float mx = fmaxf(fmaxf(v0, v1), fmaxf(v2, v3));
            mx = fmaxf(mx, __shfl_xor_sync(0xffffffffu, mx, 1));
            mx = fmaxf(mx, __shfl_xor_sync(0xffffffffu, mx, 2));
            if (lc == 0) Msl[(r0 + i) * 4 + wc] = mx;
            pv[i][0] = v0; pv[i][1] = v1; pv[i][2] = v2; pv[i][3] = v3;
        }
        __syncthreads();

        // ---- phase 2: consistent tile max -> exp, Pt store, l update ----
#pragma unroll
        for (int i = 0; i < 4; i++) {
            float4 mv = *(const float4*)(Msl + (r0 + i) * 4);
            float mx = fmaxf(fmaxf(mv.x, mv.y), fmaxf(mv.z, mv.w));
            float mnew = fmaxf(mrow[i], mx);
            float sc   = __expf(mrow[i] - mnew);
            mrow[i] = mnew;
            float e0 = __expf(pv[i][0] - mnew);
            float e1 = __expf(pv[i][1] - mnew);
            float e2 = __expf(pv[i][2] - mnew);
            float e3 = __expf(pv[i][3] - mnew);
            float rs = (e0 + e1) + (e2 + e3);
            rs += __shfl_xor_sync(0xffffffffu, rs, 1);
            rs += __shfl_xor_sync(0xffffffffu, rs, 2);
            lrow[i] = lrow[i] * sc + rs;        // slice-partial l (merged at end)
            u64 scd = dup2(sc);
            fmul2(o2[i][0], scd);
            fmul2(o2[i][1], scd);
            Pt[(c0 + 0) * 68 + r0 + i] = e0;
            Pt[(c0 + 1) * 68 + r0 + i] = e1;
            Pt[(c0 + 2) * 68 + r0 + i] = e2;
            Pt[(c0 + 3) * 68 + r0 + i] = e3;
        }
        __syncthreads();

        // ---- O += P V : p as conflict-free LDS.128 over 4 rows ----
#pragma unroll 4
        for (int jm = 0; jm < 64; jm++) {
            float4 p4 = *(const float4*)(Pt + jm * 68 + r0);
            ulonglong2 vv = *(const ulonglong2*)(Vs + jm * 68 + c0);
            u64 p0 = dup2(p4.x), p1 = dup2(p4.y), p2 = dup2(p4.z), p3 = dup2(p4.w);
            ffma2(o2[0][0], vv.x, p0); ffma2(o2[0][1], vv.y, p0);
            ffma2(o2[1][0], vv.x, p1); ffma2(o2[1][1], vv.y, p1);
            ffma2(o2[2][0], vv.x, p2); ffma2(o2[2][1], vv.y, p2);
            ffma2(o2[3][0], vv.x, p3); ffma2(o2[3][1], vv.y, p3);
        }
    }

    // ---- merge slice-partial l across the 4 wc warps, write O/l ----
    __syncthreads();
    if (lc == 0) {
#pragma unroll
        for (int i = 0; i < 4; i++)
            Msl[(r0 + i) * 4 + wc] = lrow[i];
    }
    __syncthreads();
#pragma unroll
    for (int i = 0; i < 4; i++) {
        float4 lv = *(const float4*)(Msl + (r0 + i) * 4);
        float inv = 1.0f / ((lv.x + lv.y) + (lv.z + lv.w));
        *(float4*)(g_O + (size_t)(n0 + r0 + i) * (HH * KD) + h * KD + c0) =
            make_float4(f2lo(o2[i][0]) * inv, f2hi(o2[i][0]) * inv,
                        f2lo(o2[i][1]) * inv, f2hi(o2[i][1]) * inv);
    }
}

// ---------------------------------------------------------------------------
extern "C" void kernel_launch(void* const* d_in, const int* in_sizes, int n_in,
                              void* d_out, int out_size)
{
    const float* X    = (const float*)d_in[0];
    const float* Mm   = (const float*)d_in[1];
    const int*   mask = (const int*)  d_in[2];
    const float* Wq   = (const float*)d_in[3];
    const float* Wk   = (const float*)d_in[4];
    const float* Wv   = (const float*)d_in[5];
    const float* Wo   = (const float*)d_in[6];
    float*       Y    = (float*)d_out;

    float *qp, *kp, *vp, *op;
    unsigned* mbp;
    cudaGetSymbolAddress((void**)&qp, g_Q);
    cudaGetSymbolAddress((void**)&kp, g_K);
    cudaGetSymbolAddress((void**)&vp, g_V);
    cudaGetSymbolAddress((void**)&op, g_O);
    cudaGetSymbolAddress((void**)&mbp, g_mbits);

    const int SMEM_ATTN = (4 * 64 * 68 + 256) * (int)sizeof(float);   // 70656 B
    cudaFuncSetAttribute(attn_kernel, cudaFuncAttributeMaxDynamicSharedMemorySize, SMEM_ATTN);

    dim3 blk(256);
    const long DK = (long)DD * KD, NK = (long)NN * KD, MK = (long)MM * KD;

    // Bit-pack mask
    pack_mask<<<(NN * (MM / 32)) / 256, blk>>>(mask, mbp);
    // Q: head pairs (2h, 2h+1) share the X tile
    gemm2<<<dim3(NN / 128, HH / 2), blk>>>(X, DD, Wq, Wq + DK, 2 * DK, KD,
                                           qp, qp + NK, 2 * NK, KD, DD);
    // K|V fused: same M tile feeds both projections of head h
    gemm2<<<dim3(MM / 128, HH), blk>>>(Mm, DD, Wk, Wv, DK, KD,
                                       kp, vp, MK, KD, DD);
    // Attention (heads fastest -> K/V + mask-bit L2 reuse)
    attn_kernel<<<dim3(HH, NN / 64), blk, SMEM_ATTN>>>();
    // Y = O @ Wo_flat: col-block pairs (128y, 128y+64)
    gemm2<<<dim3(NN / 128, (HH * KD) / 128), blk>>>(op, HH * KD, Wo, Wo + 64, 128, HH * KD,
                                                    Y, Y + 64, 128, HH * KD, DD);
}

// round 10
// speedup vs baseline: 1.0237x; 1.0237x over previous
#include <cuda_runtime.h>
#include <cstddef>

#define HH 16
#define DD 1024
#define KD 64
#define NN 4096
#define MM 4096

static __device__ float g_Q[(size_t)HH * NN * KD];
static __device__ float g_K[(size_t)HH * MM * KD];
static __device__ float g_V[(size_t)HH * MM * KD];
static __device__ float g_O[(size_t)NN * (HH * KD)];
static __device__ unsigned g_mbits[(size_t)NN * (MM / 32)];

typedef unsigned long long u64;

__device__ __forceinline__ u64 dup2(float x) {
    u64 r; unsigned xi = __float_as_uint(x);
    asm("mov.b64 %0, {%1, %1};" : "=l"(r) : "r"(xi));
    return r;
}
__device__ __forceinline__ u64 pack2(float lo, float hi) {
    u64 r;
    asm("mov.b64 %0, {%1, %2};" : "=l"(r) : "f"(lo), "f"(hi));
    return r;
}
__device__ __forceinline__ void ffma2(u64& d, u64 a, u64 b) {
    asm("fma.rn.f32x2 %0, %1, %2, %0;" : "+l"(d) : "l"(a), "l"(b));
}
__device__ __forceinline__ void fmul2(u64& d, u64 b) {
    asm("mul.rn.f32x2 %0, %0, %1;" : "+l"(d) : "l"(b));
}
__device__ __forceinline__ float f2lo(u64 v) { return __uint_as_float((unsigned)v); }
__device__ __forceinline__ float f2hi(u64 v) { return __uint_as_float((unsigned)(v >> 32)); }

// ---------------------------------------------------------------------------
__global__ __launch_bounds__(256) void pack_mask(const int* __restrict__ mask,
                                                 unsigned* __restrict__ bits)
{
    int idx = blockIdx.x * 256 + threadIdx.x;
    const int* p = mask + (size_t)idx * 32;
    unsigned b = 0;
#pragma unroll
    for (int u = 0; u < 8; u++) {
        int4 m = ((const int4*)p)[u];
        b |= (unsigned)(m.x != 0) << (u * 4 + 0);
        b |= (unsigned)(m.y != 0) << (u * 4 + 1);
        b |= (unsigned)(m.z != 0) << (u * 4 + 2);
        b |= (unsigned)(m.w != 0) << (u * 4 + 3);
    }
    bits[idx] = b;
}

// ---------------------------------------------------------------------------
// Fused fp32 GEMM (unchanged from R6): C[128x128] = A[128xK] * [W1 | W2]
// ---------------------------------------------------------------------------
__global__ __launch_bounds__(256) void gemm2(
    const float* __restrict__ A, int lda,
    const float* __restrict__ W1b, const float* __restrict__ W2b, long wStride, int ldw,
    float* __restrict__ C1b, float* __restrict__ C2b, long cStride, int ldc, int K)
{
    __shared__ float At[32 * 132];
    __shared__ float Ws[32 * 136];

    const int tid = threadIdx.x;
    const int tx  = tid & 15;
    const int ty  = tid >> 4;
    const int c0  = tx * 8;
    const int r0  = ty * 8;
    const int row0 = blockIdx.x * 128;
    const float* W1 = W1b + (long)blockIdx.y * wStride;
    const float* W2 = W2b + (long)blockIdx.y * wStride;

    u64 acc[4][8];
#pragma unroll
    for (int i = 0; i < 4; i++)
#pragma unroll
        for (int j = 0; j < 8; j++) acc[i][j] = 0ull;

    for (int kt = 0; kt < K; kt += 32) {
#pragma unroll
        for (int u = 0; u < 4; u++) {
            int idx = tid + u * 256;
            int r   = idx >> 3;
            int kv  = idx & 7;
            float4 v = *(const float4*)(A + (size_t)(row0 + r) * lda + kt + kv * 4);
            int rr = (r + kv * 4) & 127;
            At[(kv * 4 + 0) * 132 + rr] = v.x;
            At[(kv * 4 + 1) * 132 + rr] = v.y;
            At[(kv * 4 + 2) * 132 + rr] = v.z;
            At[(kv * 4 + 3) * 132 + rr] = v.w;
        }
#pragma unroll
        for (int u = 0; u < 4; u++) {
            int idx  = tid + u * 256;
            int half = idx >> 9;
            int kk   = (idx >> 4) & 31;
            int cv   = idx & 15;
            const float* src = (half ? W2 : W1) + (size_t)(kt + kk) * ldw + cv * 4;
            *(float4*)(Ws + kk * 136 + half * 64 + cv * 4) = *(const float4*)src;
        }
        __syncthreads();

#pragma unroll 2
        for (int kk4 = 0; kk4 < 8; kk4++) {
            int ra = (r0 + kk4 * 4) & 127;
            int rb = (r0 + 4 + kk4 * 4) & 127;
#pragma unroll
            for (int s = 0; s < 4; s++) {
                int kk = kk4 * 4 + s;
                ulonglong2 qa = *(const ulonglong2*)(At + kk * 132 + ra);
                ulonglong2 qb = *(const ulonglong2*)(At + kk * 132 + rb);
                float4 w0 = *(const float4*)(Ws + kk * 136 + c0);
                float4 w1 = *(const float4*)(Ws + kk * 136 + c0 + 4);
                u64 d0 = dup2(w0.x), d1 = dup2(w0.y), d2 = dup2(w0.z), d3 = dup2(w0.w);
                u64 d4 = dup2(w1.x), d5 = dup2(w1.y), d6 = dup2(w1.z), d7 = dup2(w1.w);
                ffma2(acc[0][0], qa.x, d0); ffma2(acc[0][1], qa.x, d1);
                ffma2(acc[0][2], qa.x, d2); ffma2(acc[0][3], qa.x, d3);
                ffma2(acc[0][4], qa.x, d4); ffma2(acc[0][5], qa.x, d5);
                ffma2(acc[0][6], qa.x, d6); ffma2(acc[0][7], qa.x, d7);
                ffma2(acc[1][0], qa.y, d0); ffma2(acc[1][1], qa.y, d1);
                ffma2(acc[1][2], qa.y, d2); ffma2(acc[1][3], qa.y, d3);
                ffma2(acc[1][4], qa.y, d4); ffma2(acc[1][5], qa.y, d5);
                ffma2(acc[1][6], qa.y, d6); ffma2(acc[1][7], qa.y, d7);
                ffma2(acc[2][0], qb.x, d0); ffma2(acc[2][1], qb.x, d1);
                ffma2(acc[2][2], qb.x, d2); ffma2(acc[2][3], qb.x, d3);
                ffma2(acc[2][4], qb.x, d4); ffma2(acc[2][5], qb.x, d5);
                ffma2(acc[2][6], qb.x, d6); ffma2(acc[2][7], qb.x, d7);
                ffma2(acc[3][0], qb.y, d0); ffma2(acc[3][1], qb.y, d1);
                ffma2(acc[3][2], qb.y, d2); ffma2(acc[3][3], qb.y, d3);
                ffma2(acc[3][4], qb.y, d4); ffma2(acc[3][5], qb.y, d5);
                ffma2(acc[3][6], qb.y, d6); ffma2(acc[3][7], qb.y, d7);
            }
        }
        __syncthreads();
    }

    float* Cp = (tx < 8)
        ? (C1b + (long)blockIdx.y * cStride + c0)
        : (C2b + (long)blockIdx.y * cStride + (c0 - 64));
#pragma unroll
    for (int i2 = 0; i2 < 4; i2++) {
        float* rlo = Cp + (size_t)(row0 + r0 + 2 * i2) * ldc;
        float* rhi = Cp + (size_t)(row0 + r0 + 2 * i2 + 1) * ldc;
        *(float4*)(rlo)     = make_float4(f2lo(acc[i2][0]), f2lo(acc[i2][1]), f2lo(acc[i2][2]), f2lo(acc[i2][3]));
        *(float4*)(rlo + 4) = make_float4(f2lo(acc[i2][4]), f2lo(acc[i2][5]), f2lo(acc[i2][6]), f2lo(acc[i2][7]));
        *(float4*)(rhi)     = make_float4(f2hi(acc[i2][0]), f2hi(acc[i2][1]), f2hi(acc[i2][2]), f2hi(acc[i2][3]));
        *(float4*)(rhi + 4) = make_float4(f2hi(acc[i2][4]), f2hi(acc[i2][5]), f2hi(acc[i2][6]), f2hi(acc[i2][7]));
    }
}

// ---------------------------------------------------------------------------
// Flash attention fp32. BM=128 x BN=64, 128 threads, 2 CTAs/SM.
// Warp = 32 rows x 64 cols; lane tile 8x8 (lr = 8-row band, lc = 8 cols).
// LDS:FMA = 1:1 in both phases. P row-pair-interleaved, conflict-free STS.64,
// read back as packed u64 FFMA2 operands. Softmax warp-local.
// ---------------------------------------------------------------------------
__global__ __launch_bounds__(128, 2) void attn_kernel(void)
{
    extern __shared__ float sm[];
    float* Qt = sm;                  // [64 kd][132 rows], rows rotated 8*(kd>>3)
    float* Kt = Qt + 64 * 132;       // [64 kd][68 cols],  cols rotated 4*(kd>>2)
    float* Vs = Kt + 64 * 68;        // [64 jm][68 v-cols]
    float* Ps = Vs + 64 * 68;        // [64 row-pair][130] = 2*jm + row-parity

    const int tid  = threadIdx.x;
    const int wrp  = tid >> 5;
    const int lane = tid & 31;
    const int lr   = lane >> 3;       // 0..3
    const int lc   = lane & 7;        // 0..7
    const int r0   = wrp * 32 + lr * 8;
    const int rp0  = r0 >> 1;         // row-pair base
    const int c0   = lc * 8;          // 8 contiguous cols
    const int h    = blockIdx.x;      // heads fastest -> K/V + mask L2 reuse
    const int n0   = blockIdx.y * 128;
    const int bsh  = 8 * (lc & 3);    // mask byte shift
    const int crot = lc >> 1;         // Ps store column rotation

    const float* Qh = g_Q + (size_t)h * NN * KD;
    const float* Kh = g_K + (size_t)h * MM * KD;
    const float* Vh = g_V + (size_t)h * MM * KD;

    // Q tile 128x64, kd-major, rotated rows (one-time)
#pragma unroll
    for (int u = 0; u < 16; u++) {
        int idx = tid + u * 128;
        int r   = idx >> 4;           // 0..127
        int kv  = idx & 15;
        float4 v = *(const float4*)(Qh + (size_t)(n0 + r) * KD + kv * 4);
        int rr = (r + 8 * (kv >> 1)) & 127;
        Qt[(kv * 4 + 0) * 132 + rr] = v.x;
        Qt[(kv * 4 + 1) * 132 + rr] = v.y;
        Qt[(kv * 4 + 2) * 132 + rr] = v.z;
        Qt[(kv * 4 + 3) * 132 + rr] = v.w;
    }

    float mrow[8], lrow[8];
    u64 o2[4][8];                     // [row-pair][col], lanes = (even,odd) rows
#pragma unroll
    for (int i = 0; i < 8; i++) { mrow[i] = -1e30f; lrow[i] = 0.0f; }
#pragma unroll
    for (int p = 0; p < 4; p++)
#pragma unroll
        for (int c = 0; c < 8; c++) o2[p][c] = 0ull;

    for (int mt = 0; mt < MM; mt += 64) {
        __syncthreads();              // prior readers of Kt/Vs done

        // K (kd-major, rotated cols) + V (row-major) tiles
#pragma unroll
        for (int u = 0; u < 8; u++) {
            int idx = tid + u * 128;
            int j   = idx >> 4;       // 0..63
            int kv  = idx & 15;
            float4 kf = *(const float4*)(Kh + (size_t)(mt + j) * KD + kv * 4);
            int jr = (j + 4 * kv) & 63;
            Kt[(kv * 4 + 0) * 68 + jr] = kf.x;
            Kt[(kv * 4 + 1) * 68 + jr] = kf.y;
            Kt[(kv * 4 + 2) * 68 + jr] = kf.z;
            Kt[(kv * 4 + 3) * 68 + jr] = kf.w;
            *(float4*)(Vs + j * 68 + kv * 4) =
                *(const float4*)(Vh + (size_t)(mt + j) * KD + kv * 4);
        }

        // Mask prefetch: one word per row (consumed post-QK, latency hidden)
        unsigned mw[8];
        {
            const unsigned* mb = g_mbits + (size_t)(n0 + r0) * (MM / 32)
                               + (mt >> 5) + (lc >> 2);
#pragma unroll
            for (int i = 0; i < 8; i++) mw[i] = mb[(size_t)i * (MM / 32)];
        }
        __syncthreads();

        // ---- S = Q K^T ----
        u64 s2[4][8];                 // [row-pair][col]
#pragma unroll
        for (int p = 0; p < 4; p++)
#pragma unroll
            for (int c = 0; c < 8; c++) s2[p][c] = 0ull;

#pragma unroll 1
        for (int kd8 = 0; kd8 < 8; kd8++) {
            const int qbase = (r0 + 8 * kd8) & 127;
#pragma unroll
            for (int t = 0; t < 8; t++) {
                const int kd = kd8 * 8 + t;
                const float* Qr = Qt + kd * 132 + qbase;
                ulonglong2 qa = *(const ulonglong2*)(Qr);       // rows r0..r0+3
                ulonglong2 qb = *(const ulonglong2*)(Qr + 4);   // rows r0+4..r0+7
                const int cc  = (c0 + 4 * (kd >> 2)) & 63;
                const int cc2 = (cc + 4) & 63;
                const float* Kr = Kt + kd * 68;
                float4 k1 = *(const float4*)(Kr + cc);
                float4 k2 = *(const float4*)(Kr + cc2);
                u64 d0 = dup2(k1.x), d1 = dup2(k1.y), d2 = dup2(k1.z), d3 = dup2(k1.w);
                u64 d4 = dup2(k2.x), d5 = dup2(k2.y), d6 = dup2(k2.z), d7 = dup2(k2.w);
                ffma2(s2[0][0], qa.x, d0); ffma2(s2[0][1], qa.x, d1);
                ffma2(s2[0][2], qa.x, d2); ffma2(s2[0][3], qa.x, d3);
                ffma2(s2[0][4], qa.x, d4); ffma2(s2[0][5], qa.x, d5);
                ffma2(s2[0][6], qa.x, d6); ffma2(s2[0][7], qa.x, d7);
                ffma2(s2[1][0], qa.y, d0); ffma2(s2[1][1], qa.y, d1);
                ffma2(s2[1][2], qa.y, d2); ffma2(s2[1][3], qa.y, d3);
                ffma2(s2[1][4], qa.y, d4); ffma2(s2[1][5], qa.y, d5);
                ffma2(s2[1][6], qa.y, d6); ffma2(s2[1][7], qa.y, d7);
                ffma2(s2[2][0], qb.x, d0); ffma2(s2[2][1], qb.x, d1);
                ffma2(s2[2][2], qb.x, d2); ffma2(s2[2][3], qb.x, d3);
                ffma2(s2[2][4], qb.x, d4); ffma2(s2[2][5], qb.x, d5);
                ffma2(s2[2][6], qb.x, d6); ffma2(s2[2][7], qb.x, d7);
                ffma2(s2[3][0], qb.y, d0); ffma2(s2[3][1], qb.y, d1);
                ffma2(s2[3][2], qb.y, d2); ffma2(s2[3][3], qb.y, d3);
                ffma2(s2[3][4], qb.y, d4); ffma2(s2[3][5], qb.y, d5);
                ffma2(s2[3][6], qb.y, d6); ffma2(s2[3][7], qb.y, d7);
            }
        }

        // ---- mask + warp-local online softmax, repack, store Ps ----
#pragma unroll
        for (int p = 0; p < 4; p++) {
            float ve[8], vo[8];
#pragma unroll
            for (int c = 0; c < 8; c++) { ve[c] = f2lo(s2[p][c]); vo[c] = f2hi(s2[p][c]); }
            unsigned be = (mw[2 * p]     >> bsh) & 0xFFu;
            unsigned bo = (mw[2 * p + 1] >> bsh) & 0xFFu;
#pragma unroll
            for (int c = 0; c < 8; c++) {
                if (!((be >> c) & 1u)) ve[c] = -1e30f;
                if (!((bo >> c) & 1u)) vo[c] = -1e30f;
            }
            // even row
            float sce, sco;
            {
                float mx = fmaxf(fmaxf(fmaxf(ve[0], ve[1]), fmaxf(ve[2], ve[3])),
                                 fmaxf(fmaxf(ve[4], ve[5]), fmaxf(ve[6], ve[7])));
                mx = fmaxf(mx, __shfl_xor_sync(0xffffffffu, mx, 1));
                mx = fmaxf(mx, __shfl_xor_sync(0xffffffffu, mx, 2));
                mx = fmaxf(mx, __shfl_xor_sync(0xffffffffu, mx, 4));
                float mnew = fmaxf(mrow[2 * p], mx);
                sce = __expf(mrow[2 * p] - mnew);
                mrow[2 * p] = mnew;
                float rs = 0.0f;
#pragma unroll
                for (int c = 0; c < 8; c++) { ve[c] = __expf(ve[c] - mnew); rs += ve[c]; }
                rs += __shfl_xor_sync(0xffffffffu, rs, 1);
                rs += __shfl_xor_sync(0xffffffffu, rs, 2);
                rs += __shfl_xor_sync(0xffffffffu, rs, 4);
                lrow[2 * p] = lrow[2 * p] * sce + rs;
            }
            // odd row
            {
                float mx = fmaxf(fmaxf(fmaxf(vo[0], vo[1]), fmaxf(vo[2], vo[3])),
                                 fmaxf(fmaxf(vo[4], vo[5]), fmaxf(vo[6], vo[7])));
                mx = fmaxf(mx, __shfl_xor_sync(0xffffffffu, mx, 1));
                mx = fmaxf(mx, __shfl_xor_sync(0xffffffffu, mx, 2));
                mx = fmaxf(mx, __shfl_xor_sync(0xffffffffu, mx, 4));
                float mnew = fmaxf(mrow[2 * p + 1], mx);
                sco = __expf(mrow[2 * p + 1] - mnew);
                mrow[2 * p + 1] = mnew;
                float rs = 0.0f;
#pragma unroll
                for (int c = 0; c < 8; c++) { vo[c] = __expf(vo[c] - mnew); rs += vo[c]; }
                rs += __shfl_xor_sync(0xffffffffu, rs, 1);
                rs += __shfl_xor_sync(0xffffffffu, rs, 2);
                rs += __shfl_xor_sync(0xffffffffu, rs, 4);
                lrow[2 * p + 1] = lrow[2 * p + 1] * sco + rs;
            }
            // rescale O pair, repack P, store (rotated cols -> conflict-free)
            u64 scp = pack2(sce, sco);
#pragma unroll
            for (int c = 0; c < 8; c++) {
                fmul2(o2[p][c], scp);
                s2[p][c] = pack2(ve[c], vo[c]);
            }
            float* Pr = Ps + (size_t)(rp0 + p) * 130;
#pragma unroll
            for (int c = 0; c < 8; c++) {
                int cs = (c + crot) & 7;
                *(u64*)(Pr + 2 * (c0 + cs)) = s2[p][cs];
            }
        }
        __syncwarp();                 // Ps is warp-private: no block barrier

        // ---- O += P V : P pairs direct u64 operands, V scalars dup'd ----
#pragma unroll 2
        for (int jm = 0; jm < 64; jm++) {
            const float* Pr = Ps + (size_t)rp0 * 130 + 2 * jm;
            u64 p0 = *(const u64*)(Pr);
            u64 p1 = *(const u64*)(Pr + 130);
            u64 p2 = *(const u64*)(Pr + 260);
            u64 p3 = *(const u64*)(Pr + 390);
            const float* Vr = Vs + jm * 68 + c0;
            float4 v1 = *(const float4*)(Vr);
            float4 v2 = *(const float4*)(Vr + 4);
            u64 d0 = dup2(v1.x), d1 = dup2(v1.y), d2 = dup2(v1.z), d3 = dup2(v1.w);
            u64 d4 = dup2(v2.x), d5 = dup2(v2.y), d6 = dup2(v2.z), d7 = dup2(v2.w);
            ffma2(o2[0][0], p0, d0); ffma2(o2[0][1], p0, d1);
            ffma2(o2[0][2], p0, d2); ffma2(o2[0][3], p0, d3);
            ffma2(o2[0][4], p0, d4); ffma2(o2[0][5], p0, d5);
            ffma2(o2[0][6], p0, d6); ffma2(o2[0][7], p0, d7);
            ffma2(o2[1][0], p1, d0); ffma2(o2[1][1], p1, d1);
            ffma2(o2[1][2], p1, d2); ffma2(o2[1][3], p1, d3);
            ffma2(o2[1][4], p1, d4); ffma2(o2[1][5], p1, d5);
            ffma2(o2[1][6], p1, d6); ffma2(o2[1][7], p1, d7);
            ffma2(o2[2][0], p2, d0); ffma2(o2[2][1], p2, d1);
            ffma2(o2[2][2], p2, d2); ffma2(o2[2][3], p2, d3);
            ffma2(o2[2][4], p2, d4); ffma2(o2[2][5], p2, d5);
            ffma2(o2[2][6], p2, d6); ffma2(o2[2][7], p2, d7);
            ffma2(o2[3][0], p3, d0); ffma2(o2[3][1], p3, d1);
            ffma2(o2[3][2], p3, d2); ffma2(o2[3][3], p3, d3);
            ffma2(o2[3][4], p3, d4); ffma2(o2[3][5], p3, d5);
            ffma2(o2[3][6], p3, d6); ffma2(o2[3][7], p3, d7);
        }
    }

    // ---- write O[n][h*64+v] = o / l ----
#pragma unroll
    for (int p = 0; p < 4; p++) {
        float inve = 1.0f / lrow[2 * p];
        float invo = 1.0f / lrow[2 * p + 1];
        float* oe = g_O + (size_t)(n0 + r0 + 2 * p)     * (HH * KD) + h * KD + c0;
        float* oo = g_O + (size_t)(n0 + r0 + 2 * p + 1) * (HH * KD) + h * KD + c0;
        *(float4*)(oe)     = make_float4(f2lo(o2[p][0]) * inve, f2lo(o2[p][1]) * inve,
                                         f2lo(o2[p][2]) * inve, f2lo(o2[p][3]) * inve);
        *(float4*)(oe + 4) = make_float4(f2lo(o2[p][4]) * inve, f2lo(o2[p][5]) * inve,
                                         f2lo(o2[p][6]) * inve, f2lo(o2[p][7]) * inve);
        *(float4*)(oo)     = make_float4(f2hi(o2[p][0]) * invo, f2hi(o2[p][1]) * invo,
                                         f2hi(o2[p][2]) * invo, f2hi(o2[p][3]) * invo);
        *(float4*)(oo + 4) = make_float4(f2hi(o2[p][4]) * invo, f2hi(o2[p][5]) * invo,
                                         f2hi(o2[p][6]) * invo, f2hi(o2[p][7]) * invo);
    }
}

// ---------------------------------------------------------------------------
extern "C" void kernel_launch(void* const* d_in, const int* in_sizes, int n_in,
                              void* d_out, int out_size)
{
    const float* X    = (const float*)d_in[0];
    const float* Mm   = (const float*)d_in[1];
    const int*   mask = (const int*)  d_in[2];
    const float* Wq   = (const float*)d_in[3];
    const float* Wk   = (const float*)d_in[4];
    const float* Wv   = (const float*)d_in[5];
    const float* Wo   = (const float*)d_in[6];
    float*       Y    = (float*)d_out;

    float *qp, *kp, *vp, *op;
    unsigned* mbp;
    cudaGetSymbolAddress((void**)&qp, g_Q);
    cudaGetSymbolAddress((void**)&kp, g_K);
    cudaGetSymbolAddress((void**)&vp, g_V);
    cudaGetSymbolAddress((void**)&op, g_O);
    cudaGetSymbolAddress((void**)&mbp, g_mbits);

    // Qt 64*132 + Kt 64*68 + Vs 64*68 + Ps 64*130 = 25472 floats = 101888 B
    const int SMEM_ATTN = (64 * 132 + 64 * 68 + 64 * 68 + 64 * 130) * (int)sizeof(float);
    cudaFuncSetAttribute(attn_kernel, cudaFuncAttributeMaxDynamicSharedMemorySize, SMEM_ATTN);

    const long DK = (long)DD * KD, NK = (long)NN * KD, MK = (long)MM * KD;

    pack_mask<<<(NN * (MM / 32)) / 256, 256>>>(mask, mbp);
    gemm2<<<dim3(NN / 128, HH / 2), 256>>>(X, DD, Wq, Wq + DK, 2 * DK, KD,
                                           qp, qp + NK, 2 * NK, KD, DD);
    gemm2<<<dim3(MM / 128, HH), 256>>>(Mm, DD, Wk, Wv, DK, KD,
                                       kp, vp, MK, KD, DD);
    attn_kernel<<<dim3(HH, NN / 128), 128, SMEM_ATTN>>>();
    gemm2<<<dim3(NN / 128, (HH * KD) / 128), 256>>>(op, HH * KD, Wo, Wo + 64, 128, HH * KD,
                                                    Y, Y + 64, 128, HH * KD, DD);
}

// round 12
// speedup vs baseline: 1.1256x; 1.0995x over previous
#include <cuda_runtime.h>
#include <cstddef>
#include <cstdint>

#define HH 16
#define DD 1024
#define KD 64
#define NN 4096
#define MM 4096

static __device__ float g_Q[(size_t)HH * NN * KD];
static __device__ float g_K[(size_t)HH * MM * KD];
static __device__ float g_V[(size_t)HH * MM * KD];
static __device__ float g_O[(size_t)NN * (HH * KD)];
static __device__ unsigned g_mbits[(size_t)NN * (MM / 32)];

typedef unsigned long long u64;

// ---- packed fp32x2 helpers ------------------------------------------------
__device__ __forceinline__ u64 dup2(float x) {
    u64 r; unsigned xi = __float_as_uint(x);
    asm("mov.b64 %0, {%1, %1};" : "=l"(r) : "r"(xi));
    return r;
}
__device__ __forceinline__ u64 pack2(float lo, float hi) {
    u64 r;
    asm("mov.b64 %0, {%1, %2};" : "=l"(r) : "f"(lo), "f"(hi));
    return r;
}
__device__ __forceinline__ void ffma2(u64& d, u64 a, u64 b) {
    asm("fma.rn.f32x2 %0, %1, %2, %0;" : "+l"(d) : "l"(a), "l"(b));
}
__device__ __forceinline__ void fmul2(u64& d, u64 b) {
    asm("mul.rn.f32x2 %0, %0, %1;" : "+l"(d) : "l"(b));
}
__device__ __forceinline__ float f2lo(u64 v) { return __uint_as_float((unsigned)v); }
__device__ __forceinline__ float f2hi(u64 v) { return __uint_as_float((unsigned)(v >> 32)); }

// ---- tf32 helpers (legacy mma.sync path: plain sm_80+ PTX) -----------------
__device__ __forceinline__ float tf32hi(float x) {
    float r; asm("cvt.rna.tf32.f32 %0, %1;" : "=f"(r) : "f"(x)); return r;
}
__device__ __forceinline__ void mma1688(float* d, const unsigned* a, const unsigned* b) {
    asm volatile(
        "mma.sync.aligned.m16n8k8.row.col.f32.tf32.tf32.f32 "
        "{%0,%1,%2,%3}, {%4,%5,%6,%7}, {%8,%9}, {%0,%1,%2,%3};"
        : "+f"(d[0]), "+f"(d[1]), "+f"(d[2]), "+f"(d[3])
        : "r"(a[0]), "r"(a[1]), "r"(a[2]), "r"(a[3]), "r"(b[0]), "r"(b[1]));
}

// ---------------------------------------------------------------------------
__global__ __launch_bounds__(256) void pack_mask(const int* __restrict__ mask,
                                                 unsigned* __restrict__ bits)
{
    int idx = blockIdx.x * 256 + threadIdx.x;
    const int* p = mask + (size_t)idx * 32;
    unsigned b = 0;
#pragma unroll
    for (int u = 0; u < 8; u++) {
        int4 m = ((const int4*)p)[u];
        b |= (unsigned)(m.x != 0) << (u * 4 + 0);
        b |= (unsigned)(m.y != 0) << (u * 4 + 1);
        b |= (unsigned)(m.z != 0) << (u * 4 + 2);
        b |= (unsigned)(m.w != 0) << (u * 4 + 3);
    }
    bits[idx] = b;
}

// ---------------------------------------------------------------------------
// tf32x3 mma.sync GEMM: C_panel[128 x 64] = A[128 x K] * W_panel[K x 64].
// 8 warps = 4 m-bands x 2 n-bands; warp tile 32x32 = 2x4 m16n8k8 frags.
// A smem [row][k] stride 36 (frag banks 4*gr+gc: conflict-free);
// B smem [k][n]  stride 72 (frag banks 8*gc+gr: conflict-free).
// hi/lo tf32 split at store; 3 MMAs (hh + hl + lh) per frag per k8.
// ---------------------------------------------------------------------------
__global__ __launch_bounds__(256) void tmma33(
    const float* __restrict__ A, int lda,
    const float* __restrict__ W, long wStride, int ldw,
    float* __restrict__ C, long cStride, int ldc, int K)
{
    extern __shared__ float smf[];
    float* Ah = smf;                  // [128][36]
    float* Al = Ah + 128 * 36;
    float* Bh = Al + 128 * 36;        // [32][72]
    float* Bl = Bh + 32 * 72;

    const int tid  = threadIdx.x;
    const int wid  = tid >> 5;
    const int lane = tid & 31;
    const int wm   = wid & 3;         // m-band (32 rows)
    const int wn   = wid >> 2;        // n-band (32 cols)
    const int m0   = wm * 32;
    const int n0   = wn * 32;
    const int gr   = lane >> 2;       // 0..7
    const int gc   = lane & 3;        // 0..3
    const int row0 = blockIdx.x * 128;
    const float* Wp = W + (long)blockIdx.y * wStride;
    float*       Cp = C + (long)blockIdx.y * cStride;

    float acc[2][4][4];
#pragma unroll
    for (int i = 0; i < 2; i++)
#pragma unroll
        for (int j = 0; j < 4; j++)
#pragma unroll
            for (int e = 0; e < 4; e++) acc[i][j][e] = 0.0f;

    for (int kt = 0; kt < K; kt += 32) {
        // Register prefetch (global latency overlaps prior chunk's MMA tail)
        float4 aP[4], bP[2];
#pragma unroll
        for (int u = 0; u < 4; u++) {
            int idx = tid + u * 256;          // 1024 float4 slots: A 128x32
            int r = idx >> 3, kv = idx & 7;
            aP[u] = *(const float4*)(A + (size_t)(row0 + r) * lda + kt + kv * 4);
        }
#pragma unroll
        for (int u = 0; u < 2; u++) {
            int idx = tid + u * 256;          // 512 slots: W 32x64
            int kk = idx >> 4, nv = idx & 15;
            bP[u] = *(const float4*)(Wp + (size_t)(kt + kk) * ldw + nv * 4);
        }
        __syncthreads();                      // prior chunk's frag reads done

        // Split + store
#pragma unroll
        for (int u = 0; u < 4; u++) {
            int idx = tid + u * 256;
            int r = idx >> 3, kv = idx & 7;
            float4 a = aP[u];
            float4 h = make_float4(tf32hi(a.x), tf32hi(a.y), tf32hi(a.z), tf32hi(a.w));
            float4 l = make_float4(tf32hi(a.x - h.x), tf32hi(a.y - h.y),
                                   tf32hi(a.z - h.z), tf32hi(a.w - h.w));
            *(float4*)(Ah + r * 36 + kv * 4) = h;
            *(float4*)(Al + r * 36 + kv * 4) = l;
        }
#pragma unroll
        for (int u = 0; u < 2; u++) {
            int idx = tid + u * 256;
            int kk = idx >> 4, nv = idx & 15;
            float4 b = bP[u];
            float4 h = make_float4(tf32hi(b.x), tf32hi(b.y), tf32hi(b.z), tf32hi(b.w));
            float4 l = make_float4(tf32hi(b.x - h.x), tf32hi(b.y - h.y),
                                   tf32hi(b.z - h.z), tf32hi(b.w - h.w));
            *(float4*)(Bh + kk * 72 + nv * 4) = h;
            *(float4*)(Bl + kk * 72 + nv * 4) = l;
        }
        __syncthreads();

        // 4 k8 steps
#pragma unroll
        for (int s = 0; s < 4; s++) {
            const int k0 = s * 8;
            unsigned ah[2][4], al[2][4];
#pragma unroll
            for (int i = 0; i < 2; i++) {
                int base = (m0 + i * 16 + gr) * 36 + k0 + gc;
                ah[i][0] = __float_as_uint(Ah[base]);
                ah[i][1] = __float_as_uint(Ah[base + 8 * 36]);
                ah[i][2] = __float_as_uint(Ah[base + 4]);
                ah[i][3] = __float_as_uint(Ah[base + 8 * 36 + 4]);
                al[i][0] = __float_as_uint(Al[base]);
                al[i][1] = __float_as_uint(Al[base + 8 * 36]);
                al[i][2] = __float_as_uint(Al[base + 4]);
                al[i][3] = __float_as_uint(Al[base + 8 * 36 + 4]);
            }
            unsigned bh[4][2], bl[4][2];
#pragma unroll
            for (int j = 0; j < 4; j++) {
                int base = (k0 + gc) * 72 + n0 + j * 8 + gr;
                bh[j][0] = __float_as_uint(Bh[base]);
                bh[j][1] = __float_as_uint(Bh[base + 4 * 72]);
                bl[j][0] = __float_as_uint(Bl[base]);
                bl[j][1] = __float_as_uint(Bl[base + 4 * 72]);
            }
#pragma unroll
            for (int i = 0; i < 2; i++)
#pragma unroll
                for (int j = 0; j < 4; j++) {
                    mma1688(acc[i][j], ah[i], bh[j]);
                    mma1688(acc[i][j], ah[i], bl[j]);
                    mma1688(acc[i][j], al[i], bh[j]);
                }
        }
    }

    // Epilogue: c0,c1 -> (row, col..col+1); c2,c3 -> (row+8, ...)
#pragma unroll
    for (int i = 0; i < 2; i++) {
        int row = row0 + m0 + i * 16 + gr;
#pragma unroll
        for (int j = 0; j < 4; j++) {
            int col = n0 + j * 8 + 2 * gc;
            *(float2*)(Cp + (size_t)row * ldc + col) =
                make_float2(acc[i][j][0], acc[i][j][1]);
            *(float2*)(Cp + (size_t)(row + 8) * ldc + col) =
                make_float2(acc[i][j][2], acc[i][j][3]);
        }
    }
}

// ---------------------------------------------------------------------------
// Flash attention fp32 (R10, unchanged: 1808 us measured).
// ---------------------------------------------------------------------------
__global__ __launch_bounds__(128, 2) void attn_kernel(void)
{
    extern __shared__ float sm[];
    float* Qt = sm;
    float* Kt = Qt + 64 * 132;
    float* Vs = Kt + 64 * 68;
    float* Ps = Vs + 64 * 68;

    const int tid  = threadIdx.x;
    const int wrp  = tid >> 5;
    const int lane = tid & 31;
    const int lr   = lane >> 3;
    const int lc   = lane & 7;
    const int r0   = wrp * 32 + lr * 8;
    const int rp0  = r0 >> 1;
    const int c0   = lc * 8;
    const int h    = blockIdx.x;
    const int n0   = blockIdx.y * 128;
    const int bsh  = 8 * (lc & 3);
    const int crot = lc >> 1;

    const float* Qh = g_Q + (size_t)h * NN * KD;
    const float* Kh = g_K + (size_t)h * MM * KD;
    const float* Vh = g_V + (size_t)h * MM * KD;

#pragma unroll
    for (int u = 0; u < 16; u++) {
        int idx = tid + u * 128;
        int r   = idx >> 4;
        int kv  = idx & 15;
        float4 v = *(const float4*)(Qh + (size_t)(n0 + r) * KD + kv * 4);
        int rr = (r + 8 * (kv >> 1)) & 127;
        Qt[(kv * 4 + 0) * 132 + rr] = v.x;
        Qt[(kv * 4 + 1) * 132 + rr] = v.y;
        Qt[(kv * 4 + 2) * 132 + rr] = v.z;
        Qt[(kv * 4 + 3) * 132 + rr] = v.w;
    }

    float mrow[8], lrow[8];
    u64 o2[4][8];
#pragma unroll
    for (int i = 0; i < 8; i++) { mrow[i] = -1e30f; lrow[i] = 0.0f; }
#pragma unroll
    for (int p = 0; p < 4; p++)
#pragma unroll
        for (int c = 0; c < 8; c++) o2[p][c] = 0ull;

    for (int mt = 0; mt < MM; mt += 64) {
        __syncthreads();
#pragma unroll
        for (int u = 0; u < 8; u++) {
            int idx = tid + u * 128;
            int j   = idx >> 4;
            int kv  = idx & 15;
            float4 kf = *(const float4*)(Kh + (size_t)(mt + j) * KD + kv * 4);
            int jr = (j + 4 * kv) & 63;
            Kt[(kv * 4 + 0) * 68 + jr] = kf.x;
            Kt[(kv * 4 + 1) * 68 + jr] = kf.y;
            Kt[(kv * 4 + 2) * 68 + jr] = kf.z;
            Kt[(kv * 4 + 3) * 68 + jr] = kf.w;
            *(float4*)(Vs + j * 68 + kv * 4) =
                *(const float4*)(Vh + (size_t)(mt + j) * KD + kv * 4);
        }
        unsigned mw[8];
        {
            const unsigned* mb = g_mbits + (size_t)(n0 + r0) * (MM / 32)
                               + (mt >> 5) + (lc >> 2);
#pragma unroll
            for (int i = 0; i < 8; i++) mw[i] = mb[(size_t)i * (MM / 32)];
        }
        __syncthreads();

        u64 s2[4][8];
#pragma unroll
        for (int p = 0; p < 4; p++)
#pragma unroll
            for (int c = 0; c < 8; c++) s2[p][c] = 0ull;

#pragma unroll 1
        for (int kd8 = 0; kd8 < 8; kd8++) {
            const int qbase = (r0 + 8 * kd8) & 127;
#pragma unroll
            for (int t = 0; t < 8; t++) {
                const int kd = kd8 * 8 + t;
                const float* Qr = Qt + kd * 132 + qbase;
                ulonglong2 qa = *(const ulonglong2*)(Qr);
                ulonglong2 qb = *(const ulonglong2*)(Qr + 4);
                const int cc  = (c0 + 4 * (kd >> 2)) & 63;
                const int cc2 = (cc + 4) & 63;
                const float* Kr = Kt + kd * 68;
                float4 k1 = *(const float4*)(Kr + cc);
                float4 k2 = *(const float4*)(Kr + cc2);
                u64 d0 = dup2(k1.x), d1 = dup2(k1.y), d2 = dup2(k1.z), d3 = dup2(k1.w);
                u64 d4 = dup2(k2.x), d5 = dup2(k2.y), d6 = dup2(k2.z), d7 = dup2(k2.w);
                ffma2(s2[0][0], qa.x, d0); ffma2(s2[0][1], qa.x, d1);
                ffma2(s2[0][2], qa.x, d2); ffma2(s2[0][3], qa.x, d3);
                ffma2(s2[0][4], qa.x, d4); ffma2(s2[0][5], qa.x, d5);
                ffma2(s2[0][6], qa.x, d6); ffma2(s2[0][7], qa.x, d7);
                ffma2(s2[1][0], qa.y, d0); ffma2(s2[1][1], qa.y, d1);
                ffma2(s2[1][2], qa.y, d2); ffma2(s2[1][3], qa.y, d3);
                ffma2(s2[1][4], qa.y, d4); ffma2(s2[1][5], qa.y, d5);
                ffma2(s2[1][6], qa.y, d6); ffma2(s2[1][7], qa.y, d7);
                ffma2(s2[2][0], qb.x, d0); ffma2(s2[2][1], qb.x, d1);
                ffma2(s2[2][2], qb.x, d2); ffma2(s2[2][3], qb.x, d3);
                ffma2(s2[2][4], qb.x, d4); ffma2(s2[2][5], qb.x, d5);
                ffma2(s2[2][6], qb.x, d6); ffma2(s2[2][7], qb.x, d7);
                ffma2(s2[3][0], qb.y, d0); ffma2(s2[3][1], qb.y, d1);
                ffma2(s2[3][2], qb.y, d2); ffma2(s2[3][3], qb.y, d3);
                ffma2(s2[3][4], qb.y, d4); ffma2(s2[3][5], qb.y, d5);
                ffma2(s2[3][6], qb.y, d6); ffma2(s2[3][7], qb.y, d7);
            }
        }

#pragma unroll
        for (int p = 0; p < 4; p++) {
            float ve[8], vo[8];
#pragma unroll
            for (int c = 0; c < 8; c++) { ve[c] = f2lo(s2[p][c]); vo[c] = f2hi(s2[p][c]); }
            unsigned be = (mw[2 * p]     >> bsh) & 0xFFu;
            unsigned bo = (mw[2 * p + 1] >> bsh) & 0xFFu;
#pragma unroll
            for (int c = 0; c < 8; c++) {
                if (!((be >> c) & 1u)) ve[c] = -1e30f;
                if (!((bo >> c) & 1u)) vo[c] = -1e30f;
            }
            float sce, sco;
            {
                float mx = fmaxf(fmaxf(fmaxf(ve[0], ve[1]), fmaxf(ve[2], ve[3])),
                                 fmaxf(fmaxf(ve[4], ve[5]), fmaxf(ve[6], ve[7])));
                mx = fmaxf(mx, __shfl_xor_sync(0xffffffffu, mx, 1));
                mx = fmaxf(mx, __shfl_xor_sync(0xffffffffu, mx, 2));
                mx = fmaxf(mx, __shfl_xor_sync(0xffffffffu, mx, 4));
                float mnew = fmaxf(mrow[2 * p], mx);
                sce = __expf(mrow[2 * p] - mnew);
                mrow[2 * p] = mnew;
                float rs = 0.0f;
#pragma unroll
                for (int c = 0; c < 8; c++) { ve[c] = __expf(ve[c] - mnew); rs += ve[c]; }
                rs += __shfl_xor_sync(0xffffffffu, rs, 1);
                rs += __shfl_xor_sync(0xffffffffu, rs, 2);
                rs += __shfl_xor_sync(0xffffffffu, rs, 4);
                lrow[2 * p] = lrow[2 * p] * sce + rs;
            }
            {
                float mx = fmaxf(fmaxf(fmaxf(vo[0], vo[1]), fmaxf(vo[2], vo[3])),
                                 fmaxf(fmaxf(vo[4], vo[5]), fmaxf(vo[6], vo[7])));
                mx = fmaxf(mx, __shfl_xor_sync(0xffffffffu, mx, 1));
                mx = fmaxf(mx, __shfl_xor_sync(0xffffffffu, mx, 2));
                mx = fmaxf(mx, __shfl_xor_sync(0xffffffffu, mx, 4));
                float mnew = fmaxf(mrow[2 * p + 1], mx);
                sco = __expf(mrow[2 * p + 1] - mnew);
                mrow[2 * p + 1] = mnew;
                float rs = 0.0f;
#pragma unroll
                for (int c = 0; c < 8; c++) { vo[c] = __expf(vo[c] - mnew); rs += vo[c]; }
                rs += __shfl_xor_sync(0xffffffffu, rs, 1);
                rs += __shfl_xor_sync(0xffffffffu, rs, 2);
                rs += __shfl_xor_sync(0xffffffffu, rs, 4);
                lrow[2 * p + 1] = lrow[2 * p + 1] * sco + rs;
            }
            u64 scp = pack2(sce, sco);
#pragma unroll
            for (int c = 0; c < 8; c++) {
                fmul2(o2[p][c], scp);
                s2[p][c] = pack2(ve[c], vo[c]);
            }
            float* Pr = Ps + (size_t)(rp0 + p) * 130;
#pragma unroll
            for (int c = 0; c < 8; c++) {
                int cs = (c + crot) & 7;
                *(u64*)(Pr + 2 * (c0 + cs)) = s2[p][cs];
            }
        }
        __syncwarp();

#pragma unroll 2
        for (int jm = 0; jm < 64; jm++) {
            const float* Pr = Ps + (size_t)rp0 * 130 + 2 * jm;
            u64 p0 = *(const u64*)(Pr);
            u64 p1 = *(const u64*)(Pr + 130);
            u64 p2 = *(const u64*)(Pr + 260);
            u64 p3 = *(const u64*)(Pr + 390);
            const float* Vr = Vs + jm * 68 + c0;
            float4 v1 = *(const float4*)(Vr);
            float4 v2 = *(const float4*)(Vr + 4);
            u64 d0 = dup2(v1.x), d1 = dup2(v1.y), d2 = dup2(v1.z), d3 = dup2(v1.w);
            u64 d4 = dup2(v2.x), d5 = dup2(v2.y), d6 = dup2(v2.z), d7 = dup2(v2.w);
            ffma2(o2[0][0], p0, d0); ffma2(o2[0][1], p0, d1);
            ffma2(o2[0][2], p0, d2); ffma2(o2[0][3], p0, d3);
            ffma2(o2[0][4], p0, d4); ffma2(o2[0][5], p0, d5);
            ffma2(o2[0][6], p0, d6); ffma2(o2[0][7], p0, d7);
            ffma2(o2[1][0], p1, d0); ffma2(o2[1][1], p1, d1);
            ffma2(o2[1][2], p1, d2); ffma2(o2[1][3], p1, d3);
            ffma2(o2[1][4], p1, d4); ffma2(o2[1][5], p1, d5);
            ffma2(o2[1][6], p1, d6); ffma2(o2[1][7], p1, d7);
            ffma2(o2[2][0], p2, d0); ffma2(o2[2][1], p2, d1);
            ffma2(o2[2][2], p2, d2); ffma2(o2[2][3], p2, d3);
            ffma2(o2[2][4], p2, d4); ffma2(o2[2][5], p2, d5);
            ffma2(o2[2][6], p2, d6); ffma2(o2[2][7], p2, d7);
            ffma2(o2[3][0], p3, d0); ffma2(o2[3][1], p3, d1);
            ffma2(o2[3][2], p3, d2); ffma2(o2[3][3], p3, d3);
            ffma2(o2[3][4], p3, d4); ffma2(o2[3][5], p3, d5);
            ffma2(o2[3][6], p3, d6); ffma2(o2[3][7], p3, d7);
        }
    }

#pragma unroll
    for (int p = 0; p < 4; p++) {
        float inve = 1.0f / lrow[2 * p];
        float invo = 1.0f / lrow[2 * p + 1];
        float* oe = g_O + (size_t)(n0 + r0 + 2 * p)     * (HH * KD) + h * KD + c0;
        float* oo = g_O + (size_t)(n0 + r0 + 2 * p + 1) * (HH * KD) + h * KD + c0;
        *(float4*)(oe)     = make_float4(f2lo(o2[p][0]) * inve, f2lo(o2[p][1]) * inve,
                                         f2lo(o2[p][2]) * inve, f2lo(o2[p][3]) * inve);
        *(float4*)(oe + 4) = make_float4(f2lo(o2[p][4]) * inve, f2lo(o2[p][5]) * inve,
                                         f2lo(o2[p][6]) * inve, f2lo(o2[p][7]) * inve);
        *(float4*)(oo)     = make_float4(f2hi(o2[p][0]) * invo, f2hi(o2[p][1]) * invo,
                                         f2hi(o2[p][2]) * invo, f2hi(o2[p][3]) * invo);
        *(float4*)(oo + 4) = make_float4(f2hi(o2[p][4]) * invo, f2hi(o2[p][5]) * invo,
                                         f2hi(o2[p][6]) * invo, f2hi(o2[p][7]) * invo);
    }
}

// ---------------------------------------------------------------------------
extern "C" void kernel_launch(void* const* d_in, const int* in_sizes, int n_in,
                              void* d_out, int out_size)
{
    const float* X    = (const float*)d_in[0];
    const float* Mm   = (const float*)d_in[1];
    const int*   mask = (const int*)  d_in[2];
    const float* Wq   = (const float*)d_in[3];
    const float* Wk   = (const float*)d_in[4];
    const float* Wv   = (const float*)d_in[5];
    const float* Wo   = (const float*)d_in[6];
    float*       Y    = (float*)d_out;

    float *qp, *kp, *vp, *op;
    unsigned* mbp;
    cudaGetSymbolAddress((void**)&qp, g_Q);
    cudaGetSymbolAddress((void**)&kp, g_K);
    cudaGetSymbolAddress((void**)&vp, g_V);
    cudaGetSymbolAddress((void**)&op, g_O);
    cudaGetSymbolAddress((void**)&mbp, g_mbits);

    const int SMEM_ATTN = (64 * 132 + 64 * 68 + 64 * 68 + 64 * 130) * (int)sizeof(float);
    cudaFuncSetAttribute(attn_kernel, cudaFuncAttributeMaxDynamicSharedMemorySize, SMEM_ATTN);
    // Ah/Al 128*36*4*2 + Bh/Bl 32*72*4*2 = 36864 + 18432 = 55296 B
    const int SMEM_TM = (128 * 36 * 2 + 32 * 72 * 2) * (int)sizeof(float);
    cudaFuncSetAttribute(tmma33, cudaFuncAttributeMaxDynamicSharedMemorySize, SMEM_TM);

    const long DK = (long)DD * KD, NK = (long)NN * KD, MK = (long)MM * KD;

    pack_mask<<<(NN * (MM / 32)) / 256, 256>>>(mask, mbp);
    // Q = X @ Wq_h (panels = heads)
    tmma33<<<dim3(NN / 128, HH), 256, SMEM_TM>>>(X,  DD, Wq, DK, KD, qp, NK, KD, DD);
    // K = M @ Wk_h
    tmma33<<<dim3(MM / 128, HH), 256, SMEM_TM>>>(Mm, DD, Wk, DK, KD, kp, MK, KD, DD);
    // V = M @ Wv_h
    tmma33<<<dim3(MM / 128, HH), 256, SMEM_TM>>>(Mm, DD, Wv, DK, KD, vp, MK, KD, DD);
    // Attention (unchanged R10)
    attn_kernel<<<dim3(HH, NN / 128), 128, SMEM_ATTN>>>();
    // Y = O @ Wo_flat (panels = 64-col blocks of the flat [1024 x 1024] Wo)
    tmma33<<<dim3(NN / 128, (HH * KD) / 64), 256, SMEM_TM>>>(op, HH * KD, Wo, 64, HH * KD,
                                                             Y, 64, HH * KD, DD);
}

// round 13
// speedup vs baseline: 1.4670x; 1.3033x over previous
#include <cuda_runtime.h>
#include <cstddef>
#include <cstdint>

#define HH 16
#define DD 1024
#define KD 64
#define NN 4096
#define MM 4096

static __device__ float g_Q[(size_t)HH * NN * KD];
static __device__ float g_K[(size_t)HH * MM * KD];
static __device__ float g_V[(size_t)HH * MM * KD];
static __device__ float g_O[(size_t)NN * (HH * KD)];
static __device__ unsigned g_mbits[(size_t)NN * (MM / 32)];

// ---- tf32 helpers (legacy mma.sync path: plain sm_80+ PTX) -----------------
__device__ __forceinline__ float tf32hi(float x) {
    float r; asm("cvt.rna.tf32.f32 %0, %1;" : "=f"(r) : "f"(x)); return r;
}
__device__ __forceinline__ void mma1688(float* d, const unsigned* a, const unsigned* b) {
    asm volatile(
        "mma.sync.aligned.m16n8k8.row.col.f32.tf32.tf32.f32 "
        "{%0,%1,%2,%3}, {%4,%5,%6,%7}, {%8,%9}, {%0,%1,%2,%3};"
        : "+f"(d[0]), "+f"(d[1]), "+f"(d[2]), "+f"(d[3])
        : "r"(a[0]), "r"(a[1]), "r"(a[2]), "r"(a[3]), "r"(b[0]), "r"(b[1]));
}

// ---------------------------------------------------------------------------
__global__ __launch_bounds__(256) void pack_mask(const int* __restrict__ mask,
                                                 unsigned* __restrict__ bits)
{
    int idx = blockIdx.x * 256 + threadIdx.x;
    const int* p = mask + (size_t)idx * 32;
    unsigned b = 0;
#pragma unroll
    for (int u = 0; u < 8; u++) {
        int4 m = ((const int4*)p)[u];
        b |= (unsigned)(m.x != 0) << (u * 4 + 0);
        b |= (unsigned)(m.y != 0) << (u * 4 + 1);
        b |= (unsigned)(m.z != 0) << (u * 4 + 2);
        b |= (unsigned)(m.w != 0) << (u * 4 + 3);
    }
    bits[idx] = b;
}

// ---------------------------------------------------------------------------
// tf32x3 mma.sync GEMM (unchanged from R12, proven).
// ---------------------------------------------------------------------------
__global__ __launch_bounds__(256) void tmma33(
    const float* __restrict__ A, int lda,
    const float* __restrict__ W, long wStride, int ldw,
    float* __restrict__ C, long cStride, int ldc, int K)
{
    extern __shared__ float smf[];
    float* Ah = smf;
    float* Al = Ah + 128 * 36;
    float* Bh = Al + 128 * 36;
    float* Bl = Bh + 32 * 72;

    const int tid  = threadIdx.x;
    const int wid  = tid >> 5;
    const int lane = tid & 31;
    const int wm   = wid & 3;
    const int wn   = wid >> 2;
    const int m0   = wm * 32;
    const int n0   = wn * 32;
    const int gr   = lane >> 2;
    const int gc   = lane & 3;
    const int row0 = blockIdx.x * 128;
    const float* Wp = W + (long)blockIdx.y * wStride;
    float*       Cp = C + (long)blockIdx.y * cStride;

    float acc[2][4][4];
#pragma unroll
    for (int i = 0; i < 2; i++)
#pragma unroll
        for (int j = 0; j < 4; j++)
#pragma unroll
            for (int e = 0; e < 4; e++) acc[i][j][e] = 0.0f;

    for (int kt = 0; kt < K; kt += 32) {
        float4 aP[4], bP[2];
#pragma unroll
        for (int u = 0; u < 4; u++) {
            int idx = tid + u * 256;
            int r = idx >> 3, kv = idx & 7;
            aP[u] = *(const float4*)(A + (size_t)(row0 + r) * lda + kt + kv * 4);
        }
#pragma unroll
        for (int u = 0; u < 2; u++) {
            int idx = tid + u * 256;
            int kk = idx >> 4, nv = idx & 15;
            bP[u] = *(const float4*)(Wp + (size_t)(kt + kk) * ldw + nv * 4);
        }
        __syncthreads();

#pragma unroll
        for (int u = 0; u < 4; u++) {
            int idx = tid + u * 256;
            int r = idx >> 3, kv = idx & 7;
            float4 a = aP[u];
            float4 h = make_float4(tf32hi(a.x), tf32hi(a.y), tf32hi(a.z), tf32hi(a.w));
            float4 l = make_float4(tf32hi(a.x - h.x), tf32hi(a.y - h.y),
                                   tf32hi(a.z - h.z), tf32hi(a.w - h.w));
            *(float4*)(Ah + r * 36 + kv * 4) = h;
            *(float4*)(Al + r * 36 + kv * 4) = l;
        }
#pragma unroll
        for (int u = 0; u < 2; u++) {
            int idx = tid + u * 256;
            int kk = idx >> 4, nv = idx & 15;
            float4 b = bP[u];
            float4 h = make_float4(tf32hi(b.x), tf32hi(b.y), tf32hi(b.z), tf32hi(b.w));
            float4 l = make_float4(tf32hi(b.x - h.x), tf32hi(b.y - h.y),
                                   tf32hi(b.z - h.z), tf32hi(b.w - h.w));
            *(float4*)(Bh + kk * 72 + nv * 4) = h;
            *(float4*)(Bl + kk * 72 + nv * 4) = l;
        }
        __syncthreads();

#pragma unroll
        for (int s = 0; s < 4; s++) {
            const int k0 = s * 8;
            unsigned ah[2][4], al[2][4];
#pragma unroll
            for (int i = 0; i < 2; i++) {
                int base = (m0 + i * 16 + gr) * 36 + k0 + gc;
                ah[i][0] = __float_as_uint(Ah[base]);
                ah[i][1] = __float_as_uint(Ah[base + 8 * 36]);
                ah[i][2] = __float_as_uint(Ah[base + 4]);
                ah[i][3] = __float_as_uint(Ah[base + 8 * 36 + 4]);
                al[i][0] = __float_as_uint(Al[base]);
                al[i][1] = __float_as_uint(Al[base + 8 * 36]);
                al[i][2] = __float_as_uint(Al[base + 4]);
                al[i][3] = __float_as_uint(Al[base + 8 * 36 + 4]);
            }
            unsigned bh[4][2], bl[4][2];
#pragma unroll
            for (int j = 0; j < 4; j++) {
                int base = (k0 + gc) * 72 + n0 + j * 8 + gr;
                bh[j][0] = __float_as_uint(Bh[base]);
                bh[j][1] = __float_as_uint(Bh[base + 4 * 72]);
                bl[j][0] = __float_as_uint(Bl[base]);
                bl[j][1] = __float_as_uint(Bl[base + 4 * 72]);
            }
#pragma unroll
            for (int i = 0; i < 2; i++)
#pragma unroll
                for (int j = 0; j < 4; j++) {
                    mma1688(acc[i][j], ah[i], bh[j]);
                    mma1688(acc[i][j], ah[i], bl[j]);
                    mma1688(acc[i][j], al[i], bh[j]);
                }
        }
    }

#pragma unroll
    for (int i = 0; i < 2; i++) {
        int row = row0 + m0 + i * 16 + gr;
#pragma unroll
        for (int j = 0; j < 4; j++) {
            int col = n0 + j * 8 + 2 * gc;
            *(float2*)(Cp + (size_t)row * ldc + col) =
                make_float2(acc[i][j][0], acc[i][j][1]);
            *(float2*)(Cp + (size_t)(row + 8) * ldc + col) =
                make_float2(acc[i][j][2], acc[i][j][3]);
        }
    }
}

// ---------------------------------------------------------------------------
// Tensor-core flash attention (mma.sync tf32).
// BM=128 x BN=32, 256 threads = 8 warps; warp = 16 rows x 32 cols
// (1 m-frag x 4 n-frags) -> softmax warp-local, P warp-private.
// QK: tf32x3 (Q split at frag load; K hi/lo staged in smem).
// PV: P single tf32 (denominator computed from ROUNDED P -> common-mode
// rounding cancels), V hi/lo x2 staged in smem.
// Frag maps identical to tmma33 (proven): A banks 4gr+gc, B banks 8gc+gr.
// ---------------------------------------------------------------------------
__global__ __launch_bounds__(256, 2) void attn_mma(void)
{
    extern __shared__ float smf[];
    float* Qs = smf;                   // [128][68] f32 (split at frag load)
    float* Kh = Qs + 128 * 68;         // [32 j][68 kd] tf32-hi
    float* Kl = Kh + 32 * 68;          // [32 j][68 kd] tf32-lo
    float* Vh = Kl + 32 * 68;          // [32 jm][72 v] tf32-hi
    float* Vl = Vh + 32 * 72;          // [32 jm][72 v] tf32-lo
    float* Ps = Vl + 32 * 72;          // [128][36] rounded P

    const int tid  = threadIdx.x;
    const int wid  = tid >> 5;
    const int lane = tid & 31;
    const int gr   = lane >> 2;
    const int gc   = lane & 3;
    const int wm   = wid * 16;         // warp row band
    const int h    = blockIdx.x;       // heads fastest -> K/V + mask L2 reuse
    const int nq0  = blockIdx.y * 128;

    const float* Qg = g_Q + (size_t)h * NN * KD;
    const float* Kg = g_K + (size_t)h * MM * KD;
    const float* Vg = g_V + (size_t)h * MM * KD;

    // Stage Q tile once (f32, coalesced)
#pragma unroll
    for (int u = 0; u < 8; u++) {
        int idx = tid + u * 256;
        int r = idx >> 4, kv = idx & 15;
        *(float4*)(Qs + r * 68 + kv * 4) =
            *(const float4*)(Qg + (size_t)(nq0 + r) * KD + kv * 4);
    }

    float mrow[2] = { -1e30f, -1e30f };
    float lrow[2] = { 0.0f, 0.0f };
    float oc[8][4];
#pragma unroll
    for (int n = 0; n < 8; n++)
#pragma unroll
        for (int e = 0; e < 4; e++) oc[n][e] = 0.0f;

    const int row0 = nq0 + wm + gr;

    for (int mt = 0; mt < MM; mt += 32) {
        __syncthreads();               // prior tile's readers of Kh/Kl/Vh/Vl done

        // Stage K, V tiles (split hi/lo; both are natural B layouts)
#pragma unroll
        for (int u = 0; u < 2; u++) {
            int idx = tid + u * 256;
            int j = idx >> 4, kv = idx & 15;
            float4 k4 = *(const float4*)(Kg + (size_t)(mt + j) * KD + kv * 4);
            float4 kh = make_float4(tf32hi(k4.x), tf32hi(k4.y), tf32hi(k4.z), tf32hi(k4.w));
            float4 kl = make_float4(tf32hi(k4.x - kh.x), tf32hi(k4.y - kh.y),
                                    tf32hi(k4.z - kh.z), tf32hi(k4.w - kh.w));
            *(float4*)(Kh + j * 68 + kv * 4) = kh;
            *(float4*)(Kl + j * 68 + kv * 4) = kl;
            float4 v4 = *(const float4*)(Vg + (size_t)(mt + j) * KD + kv * 4);
            float4 vh = make_float4(tf32hi(v4.x), tf32hi(v4.y), tf32hi(v4.z), tf32hi(v4.w));
            float4 vl = make_float4(tf32hi(v4.x - vh.x), tf32hi(v4.y - vh.y),
                                    tf32hi(v4.z - vh.z), tf32hi(v4.w - vh.w));
            *(float4*)(Vh + j * 72 + kv * 4) = vh;
            *(float4*)(Vl + j * 72 + kv * 4) = vl;
        }

        // Mask word prefetch (one 32-bit word covers this BN=32 tile per row)
        const unsigned mw0 = g_mbits[(size_t)row0 * (MM / 32) + (mt >> 5)];
        const unsigned mw1 = g_mbits[(size_t)(row0 + 8) * (MM / 32) + (mt >> 5)];
        __syncthreads();

        // ---- S = Q K^T (tf32 x3) ----
        float sc[4][4];
#pragma unroll
        for (int j = 0; j < 4; j++)
#pragma unroll
            for (int e = 0; e < 4; e++) sc[j][e] = 0.0f;

#pragma unroll
        for (int s = 0; s < 8; s++) {
            const int k0 = s * 8;
            const float* Qr = Qs + (wm + gr) * 68 + k0 + gc;
            float f0 = Qr[0], f1 = Qr[8 * 68], f2 = Qr[4], f3 = Qr[8 * 68 + 4];
            float h0 = tf32hi(f0), h1 = tf32hi(f1), h2 = tf32hi(f2), h3 = tf32hi(f3);
            unsigned qh[4] = { __float_as_uint(h0), __float_as_uint(h1),
                               __float_as_uint(h2), __float_as_uint(h3) };
            unsigned ql[4] = { __float_as_uint(tf32hi(f0 - h0)), __float_as_uint(tf32hi(f1 - h1)),
                               __float_as_uint(tf32hi(f2 - h2)), __float_as_uint(tf32hi(f3 - h3)) };
#pragma unroll
            for (int j = 0; j < 4; j++) {
                int kb = (j * 8 + gr) * 68 + k0 + gc;
                unsigned bh[2] = { __float_as_uint(Kh[kb]), __float_as_uint(Kh[kb + 4]) };
                unsigned bl[2] = { __float_as_uint(Kl[kb]), __float_as_uint(Kl[kb + 4]) };
                mma1688(sc[j], qh, bh);
                mma1688(sc[j], qh, bl);
                mma1688(sc[j], ql, bh);
            }
        }

        // ---- mask + online softmax (warp-local; rows gr and gr+8) ----
        float scl[2];
#pragma unroll
        for (int e = 0; e < 2; e++) {
            const unsigned w = e ? mw1 : mw0;
            float v[8];
#pragma unroll
            for (int j = 0; j < 4; j++) {
                v[2 * j]     = sc[j][2 * e];
                v[2 * j + 1] = sc[j][2 * e + 1];
                unsigned b2 = (w >> (8 * j + 2 * gc)) & 3u;
                if (!(b2 & 1u)) v[2 * j]     = -1e30f;
                if (!(b2 & 2u)) v[2 * j + 1] = -1e30f;
            }
            float mx = fmaxf(fmaxf(fmaxf(v[0], v[1]), fmaxf(v[2], v[3])),
                             fmaxf(fmaxf(v[4], v[5]), fmaxf(v[6], v[7])));
            mx = fmaxf(mx, __shfl_xor_sync(0xffffffffu, mx, 1));
            mx = fmaxf(mx, __shfl_xor_sync(0xffffffffu, mx, 2));
            float mnew = fmaxf(mrow[e], mx);
            scl[e] = __expf(mrow[e] - mnew);
            mrow[e] = mnew;
            float rs = 0.0f;
#pragma unroll
            for (int t = 0; t < 8; t++) {
                float p = tf32hi(__expf(v[t] - mnew));   // round BEFORE summing:
                v[t] = p;                                // denominator consistent with MMA
                rs += p;
            }
            rs += __shfl_xor_sync(0xffffffffu, rs, 1);
            rs += __shfl_xor_sync(0xffffffffu, rs, 2);
            lrow[e] = lrow[e] * scl[e] + rs;
#pragma unroll
            for (int j = 0; j < 4; j++) {
                sc[j][2 * e]     = v[2 * j];
                sc[j][2 * e + 1] = v[2 * j + 1];
            }
        }
        // Rescale O
#pragma unroll
        for (int n = 0; n < 8; n++) {
            oc[n][0] *= scl[0]; oc[n][1] *= scl[0];
            oc[n][2] *= scl[1]; oc[n][3] *= scl[1];
        }
        // Store P (warp-private rows)
        {
            float* Pr0 = Ps + (wm + gr) * 36;
            float* Pr1 = Ps + (wm + gr + 8) * 36;
#pragma unroll
            for (int j = 0; j < 4; j++) {
                *(float2*)(Pr0 + 8 * j + 2 * gc) = make_float2(sc[j][0], sc[j][1]);
                *(float2*)(Pr1 + 8 * j + 2 * gc) = make_float2(sc[j][2], sc[j][3]);
            }
        }
        __syncwarp();

        // ---- O += P V (P tf32, V hi/lo x2) ----
#pragma unroll
        for (int kc = 0; kc < 4; kc++) {
            const int k0 = kc * 8;
            int pb = (wm + gr) * 36 + k0 + gc;
            unsigned pa[4] = { __float_as_uint(Ps[pb]),
                               __float_as_uint(Ps[pb + 8 * 36]),
                               __float_as_uint(Ps[pb + 4]),
                               __float_as_uint(Ps[pb + 8 * 36 + 4]) };
#pragma unroll
            for (int n = 0; n < 8; n++) {
                int vb = (k0 + gc) * 72 + n * 8 + gr;
                unsigned bvh[2] = { __float_as_uint(Vh[vb]), __float_as_uint(Vh[vb + 4 * 72]) };
                unsigned bvl[2] = { __float_as_uint(Vl[vb]), __float_as_uint(Vl[vb + 4 * 72]) };
                mma1688(oc[n], pa, bvh);
                mma1688(oc[n], pa, bvl);
            }
        }
    }

    // ---- write O/l ----
    const float i0 = 1.0f / lrow[0];
    const float i1 = 1.0f / lrow[1];
    float* ob = g_O + (size_t)row0 * (HH * KD) + h * KD;
#pragma unroll
    for (int n = 0; n < 8; n++) {
        *(float2*)(ob + n * 8 + 2 * gc) =
            make_float2(oc[n][0] * i0, oc[n][1] * i0);
        *(float2*)(ob + (size_t)8 * (HH * KD) + n * 8 + 2 * gc) =
            make_float2(oc[n][2] * i1, oc[n][3] * i1);
    }
}

// ---------------------------------------------------------------------------
extern "C" void kernel_launch(void* const* d_in, const int* in_sizes, int n_in,
                              void* d_out, int out_size)
{
    const float* X    = (const float*)d_in[0];
    const float* Mm   = (const float*)d_in[1];
    const int*   mask = (const int*)  d_in[2];
    const float* Wq   = (const float*)d_in[3];
    const float* Wk   = (const float*)d_in[4];
    const float* Wv   = (const float*)d_in[5];
    const float* Wo   = (const float*)d_in[6];
    float*       Y    = (float*)d_out;

    float *qp, *kp, *vp, *op;
    unsigned* mbp;
    cudaGetSymbolAddress((void**)&qp, g_Q);
    cudaGetSymbolAddress((void**)&kp, g_K);
    cudaGetSymbolAddress((void**)&vp, g_V);
    cudaGetSymbolAddress((void**)&op, g_O);
    cudaGetSymbolAddress((void**)&mbp, g_mbits);

    // Qs 128*68 + Kh/Kl 2*32*68 + Vh/Vl 2*32*72 + Ps 128*36 = 22272 floats
    const int SMEM_AT = (128 * 68 + 2 * 32 * 68 + 2 * 32 * 72 + 128 * 36) * (int)sizeof(float);
    cudaFuncSetAttribute(attn_mma, cudaFuncAttributeMaxDynamicSharedMemorySize, SMEM_AT);
    const int SMEM_TM = (128 * 36 * 2 + 32 * 72 * 2) * (int)sizeof(float);
    cudaFuncSetAttribute(tmma33, cudaFuncAttributeMaxDynamicSharedMemorySize, SMEM_TM);

    const long DK = (long)DD * KD, NK = (long)NN * KD, MK = (long)MM * KD;

    pack_mask<<<(NN * (MM / 32)) / 256, 256>>>(mask, mbp);
    tmma33<<<dim3(NN / 128, HH), 256, SMEM_TM>>>(X,  DD, Wq, DK, KD, qp, NK, KD, DD);
    tmma33<<<dim3(MM / 128, HH), 256, SMEM_TM>>>(Mm, DD, Wk, DK, KD, kp, MK, KD, DD);
    tmma33<<<dim3(MM / 128, HH), 256, SMEM_TM>>>(Mm, DD, Wv, DK, KD, vp, MK, KD, DD);
    attn_mma<<<dim3(HH, NN / 128), 256, SMEM_AT>>>();
    tmma33<<<dim3(NN / 128, (HH * KD) / 64), 256, SMEM_TM>>>(op, HH * KD, Wo, 64, HH * KD,
                                                             Y, 64, HH * KD, DD);
}